// round 4
// baseline (speedup 1.0000x reference)
#include <cuda_runtime.h>
#include <cstdint>

#define BB    2048
#define TSEQ  512
#define HH    51
#define TTOT  544      // TSEQ + 32 future
#define EPC   16       // batch elements per CTA
#define NCTA  128      // EPC * NCTA == BB
#define NTHR  512      // 2 groups x 64 j x 2 gate-split x 2 k-split
#define MPT   8        // elements per thread
#define HROW  56       // floats per element row in h arrays (52 used, 16B aligned)

// weight layout: addr = q*WQ + j*WJ + ks*16 + gs*8 + kb*4 + pair*2 + s
#define WJ     36               // words per (q, j) slot (32 used, conflict-free pad)
#define WQ     (HH * WJ)        // 1836 words per q-slab (51 j rows)
#define W_SZ   (7 * WQ)         // 12852 words per weight matrix
#define XS_SZ  (EPC * TSEQ)     // 8192
#define HD_SZ  (EPC * HROW)     // 896
#define SM_FLOATS (3*W_SZ + XS_SZ + 2*HD_SZ + 256 + 256 + 256 + 64 + 16)
#define SM_BYTES  (SM_FLOATS * 4)

// ---------------- packed f32x2 helpers ----------------
__device__ __forceinline__ unsigned long long ffma2(unsigned long long a,
                                                    unsigned long long b,
                                                    unsigned long long c) {
    unsigned long long d;
    asm("fma.rn.f32x2 %0, %1, %2, %3;" : "=l"(d) : "l"(a), "l"(b), "l"(c));
    return d;
}
__device__ __forceinline__ unsigned long long pack2(float lo, float hi) {
    unsigned long long d;
    asm("mov.b64 %0, {%1, %2};" : "=l"(d) : "f"(lo), "f"(hi));
    return d;
}
__device__ __forceinline__ float2 unpack2(unsigned long long v) {
    float2 r;
    asm("mov.b64 {%0, %1}, %2;" : "=f"(r.x), "=f"(r.y) : "l"(v));
    return r;
}
__device__ __forceinline__ float sigf(float x) {
    return __fdividef(1.0f, 1.0f + __expf(-x));
}
__device__ __forceinline__ float tanhf_fast(float x) {
    return __fdividef(2.0f, 1.0f + __expf(-2.0f * x)) - 1.0f;
}

// acc{A,B}[m] += W[j, gates(2gs..2gs+1), k-half(ks)] . h[e0+m, k-half(ks)]
__device__ __forceinline__ void matvec_acc(const float* __restrict__ Wthr,
                                           const float* __restrict__ hthr,
                                           unsigned long long aA[MPT],
                                           unsigned long long aB[MPT]) {
#pragma unroll
    for (int q = 0; q < 7; q++) {            // q covers 4 k of my half
        ulonglong2 w0 = *(const ulonglong2*)(Wthr + q * WQ);      // kb0: {gA},{gB}
        ulonglong2 w1 = *(const ulonglong2*)(Wthr + q * WQ + 4);  // kb1: {gA},{gB}
#pragma unroll
        for (int m = 0; m < MPT; m++) {
            ulonglong2 hp = *(const ulonglong2*)(hthr + m * HROW + q * 4);
            aA[m] = ffma2(w0.x, hp.x, aA[m]);
            aB[m] = ffma2(w0.y, hp.x, aB[m]);
            aA[m] = ffma2(w1.x, hp.y, aA[m]);
            aB[m] = ffma2(w1.y, hp.y, aB[m]);
        }
    }
}

__global__ void __launch_bounds__(NTHR, 1)
lstm_seq_kernel(const float* __restrict__ input,
                const float* __restrict__ Wih1, const float* __restrict__ Whh1,
                const float* __restrict__ bih1, const float* __restrict__ bhh1,
                const float* __restrict__ Wih2, const float* __restrict__ Whh2,
                const float* __restrict__ bih2, const float* __restrict__ bhh2,
                const float* __restrict__ Wlin, const float* __restrict__ blin,
                float* __restrict__ out) {
    extern __shared__ float sm[];
    float* W1    = sm;                 // k-split weight layout (see defines)
    float* W2i   = W1  + W_SZ;
    float* W2h   = W2i + W_SZ;
    float* xs    = W2h + W_SZ;         // [16][512]
    float* hd1   = xs  + XS_SZ;        // [16][56]
    float* hd2   = hd1 + HD_SZ;        // [16][56]
    float* wih1q = hd2 + HD_SZ;        // [64][4]
    float* b1q   = wih1q + 256;        // [64][4]
    float* b2q   = b1q   + 256;        // [64][4]
    float* wlin  = b2q   + 256;        // [64]
    float* outb  = wlin  + 64;         // [16]

    const int tid = threadIdx.x;
    const int g   = tid >> 8;            // group 0..1 (8 elements each)
    const int r   = tid & 255;
    const int j   = r >> 2;              // hidden unit 0..63 (active < 51)
    const int gs  = (r >> 1) & 1;        // gate split: 0 -> (i,f), 1 -> (g,o)
    const int ks  = r & 1;               // k split: 0 -> k[0..25], 1 -> k[26..50]
    const int jj  = (j < HH) ? j : (HH - 1);
    const int b0  = blockIdx.x * EPC;
    const int e0  = g * MPT;

    // activation constants: a1 = kA / (1 + exp(kmul*z)) + kB
    const float kmul = gs ? -2.0f : -1.0f;
    const float kA   = gs ?  2.0f :  1.0f;
    const float kB   = gs ? -1.0f :  0.0f;
    const float ksf  = (ks == 0) ? 1.0f : 0.0f;   // bias/x applied once

    // ---------- one-time init ----------
    // zero weight regions (covers padding), then fill
    for (int idx = tid; idx < 3 * W_SZ; idx += NTHR) W1[idx] = 0.f;
    __syncthreads();
    // fill: iterate (q, jr, kss, gss) -> 8 floats each
    for (int idx = tid; idx < 7 * HH * 4; idx += NTHR) {
        int q   = idx / (HH * 4);
        int rem = idx - q * (HH * 4);
        int jr  = rem >> 2;
        int kss = (rem >> 1) & 1;
        int gss = rem & 1;
        int o   = q * WQ + jr * WJ + kss * 16 + gss * 8;
#pragma unroll
        for (int kb = 0; kb < 2; kb++) {
#pragma unroll
            for (int p = 0; p < 2; p++) {     // gate within pair
#pragma unroll
                for (int s = 0; s < 2; s++) {
                    int k  = (kss ? 24 : 0) + 4 * q + 2 * kb + s;
                    bool ok = kss ? (k >= 26 && k < HH) : (k < 26);
                    int gg = gss * 2 + p;
                    int rr = gg * HH + jr;
                    float v1 = ok ? Whh1[rr * HH + k] : 0.f;
                    float v2 = ok ? Wih2[rr * HH + k] : 0.f;
                    float v3 = ok ? Whh2[rr * HH + k] : 0.f;
                    int oo = o + kb * 4 + p * 2 + s;
                    W1 [oo] = v1;
                    W2i[oo] = v2;
                    W2h[oo] = v3;
                }
            }
        }
    }
    if (tid < 64) {
#pragma unroll
        for (int gg = 0; gg < 4; gg++) {
            bool ok = tid < HH;
            wih1q[tid * 4 + gg] = ok ? Wih1[gg * HH + tid] : 0.f;
            b1q  [tid * 4 + gg] = ok ? (bih1[gg * HH + tid] + bhh1[gg * HH + tid]) : 0.f;
            b2q  [tid * 4 + gg] = ok ? (bih2[gg * HH + tid] + bhh2[gg * HH + tid]) : 0.f;
        }
        wlin[tid] = (tid < HH) ? Wlin[tid] : 0.f;
    }
    for (int idx = tid; idx < XS_SZ; idx += NTHR) {
        int e = idx >> 9, tc = idx & 511;
        xs[idx] = input[(size_t)(b0 + e) * TSEQ + tc];
    }
    for (int idx = tid; idx < HD_SZ; idx += NTHR) { hd1[idx] = 0.f; hd2[idx] = 0.f; }
    const float blin_r = blin[0];
    __syncthreads();

    float c1[MPT], c2[MPT];
#pragma unroll
    for (int m = 0; m < MPT; m++) { c1[m] = 0.f; c2[m] = 0.f; }

    const float*  W1t  = W1  + jj * WJ + ks * 16 + gs * 8;
    const float*  W2it = W2i + jj * WJ + ks * 16 + gs * 8;
    const float*  W2ht = W2h + jj * WJ + ks * 16 + gs * 8;
    const float2  wxp  = *(const float2*)(wih1q + jj * 4 + gs * 2);
    const float2  bp1  = *(const float2*)(b1q   + jj * 4 + gs * 2);
    const float2  bp2  = *(const float2*)(b2q   + jj * 4 + gs * 2);
    const bool    own  = ((r & 3) == 0) && (j < HH);   // gs0,ks0 owner lane
    const float   wl   = own ? wlin[j] : 0.f;
    const float*  hd1t = hd1 + e0 * HROW + ks * 24;    // k-half offset (16B aligned)
    const float*  hd2t = hd2 + e0 * HROW + ks * 24;

    // ---------- sequential scan ----------
    for (int t = 0; t < TTOT; t++) {
        float xm[MPT];
        if (t < TSEQ) {
#pragma unroll
            for (int m = 0; m < MPT; m++) xm[m] = xs[(e0 + m) * TSEQ + t];
        } else {
#pragma unroll
            for (int m = 0; m < MPT; m++) xm[m] = outb[e0 + m];   // out[t-1]
        }

        // ---- layer 1 ----
        unsigned long long aA[MPT], aB[MPT];
#pragma unroll
        for (int m = 0; m < MPT; m++) {
            aA[m] = pack2(ksf * fmaf(wxp.x, xm[m], bp1.x), 0.f);
            aB[m] = pack2(ksf * fmaf(wxp.y, xm[m], bp1.y), 0.f);
        }
        matvec_acc(W1t, hd1t, aA, aB);

        float h1n[MPT];
#pragma unroll
        for (int m = 0; m < MPT; m++) {
            float2 va = unpack2(aA[m]);
            float2 vb = unpack2(aB[m]);
            float zA = va.x + va.y, zB = vb.x + vb.y;
            zA += __shfl_xor_sync(0xffffffffu, zA, 1);   // combine k-halves
            zB += __shfl_xor_sync(0xffffffffu, zB, 1);
            float a1 = kA * __fdividef(1.0f, 1.0f + __expf(kmul * zA)) + kB; // i|g
            float a2 = sigf(zB);                                             // f|o
            float g_r = __shfl_xor_sync(0xffffffffu, a1, 2);
            float o_r = __shfl_xor_sync(0xffffffffu, a2, 2);
            c1[m]  = a2 * c1[m] + a1 * g_r;       // valid at gs0 lanes
            h1n[m] = o_r * tanhf_fast(c1[m]);
        }
        __syncthreads();                                  // S1
        if (own) {
#pragma unroll
            for (int m = 0; m < MPT; m++)
                hd1[(e0 + m) * HROW + j] = h1n[m];
        }
        if (tid < EPC) outb[tid] = blin_r;
        __syncthreads();                                  // S2

        // ---- layer 2 ----
#pragma unroll
        for (int m = 0; m < MPT; m++) {
            aA[m] = pack2(ksf * bp2.x, 0.f);
            aB[m] = pack2(ksf * bp2.y, 0.f);
        }
        matvec_acc(W2it, hd1t, aA, aB);   // W_ih2 @ h1(new)
        matvec_acc(W2ht, hd2t, aA, aB);   // W_hh2 @ h2(old)

        float h2n[MPT];
#pragma unroll
        for (int m = 0; m < MPT; m++) {
            float2 va = unpack2(aA[m]);
            float2 vb = unpack2(aB[m]);
            float zA = va.x + va.y, zB = vb.x + vb.y;
            zA += __shfl_xor_sync(0xffffffffu, zA, 1);
            zB += __shfl_xor_sync(0xffffffffu, zB, 1);
            float a1 = kA * __fdividef(1.0f, 1.0f + __expf(kmul * zA)) + kB;
            float a2 = sigf(zB);
            float g_r = __shfl_xor_sync(0xffffffffu, a1, 2);
            float o_r = __shfl_xor_sync(0xffffffffu, a2, 2);
            c2[m]  = a2 * c2[m] + a1 * g_r;
            h2n[m] = o_r * tanhf_fast(c2[m]);
        }
        __syncthreads();                                  // S3
        if (own) {
#pragma unroll
            for (int m = 0; m < MPT; m++)
                hd2[(e0 + m) * HROW + j] = h2n[m];
        }
        // out[e] = sum_j wlin[j]*h2[j] + blin
#pragma unroll
        for (int m = 0; m < MPT; m++) {
            float p = wl * h2n[m];                        // wl==0 on non-owner lanes
#pragma unroll
            for (int off = 16; off > 0; off >>= 1)
                p += __shfl_xor_sync(0xffffffffu, p, off);
            if ((tid & 31) == 0) atomicAdd(&outb[e0 + m], p);
        }
        __syncthreads();                                  // S4
        if (tid < EPC)
            out[(size_t)(b0 + tid) * TTOT + t] = outb[tid];
    }
}

extern "C" void kernel_launch(void* const* d_in, const int* in_sizes, int n_in,
                              void* d_out, int out_size) {
    const float* input = (const float*)d_in[0];
    const float* Wih1  = (const float*)d_in[1];
    const float* Whh1  = (const float*)d_in[2];
    const float* bih1  = (const float*)d_in[3];
    const float* bhh1  = (const float*)d_in[4];
    const float* Wih2  = (const float*)d_in[5];
    const float* Whh2  = (const float*)d_in[6];
    const float* bih2  = (const float*)d_in[7];
    const float* bhh2  = (const float*)d_in[8];
    const float* Wlin  = (const float*)d_in[9];
    const float* blin  = (const float*)d_in[10];
    // d_in[11] = "future" (=32), baked in as a constant.

    cudaFuncSetAttribute(lstm_seq_kernel,
                         cudaFuncAttributeMaxDynamicSharedMemorySize, SM_BYTES);
    lstm_seq_kernel<<<NCTA, NTHR, SM_BYTES>>>(input, Wih1, Whh1, bih1, bhh1,
                                              Wih2, Whh2, bih2, bhh2,
                                              Wlin, blin, (float*)d_out);
}